// round 5
// baseline (speedup 1.0000x reference)
#include <cuda_runtime.h>

// Seq2Seq GRU encoder/decoder, persistent per-CTA batch-slice kernel.
// R3: packed fma.rn.f32x2 along the gate-column dimension; h/x stored
// duplicated in smem so pair operands need no per-iteration packing.
// (R2 retry: fixed Smem alignment — all vector-accessed arrays __align__(16).)
#define SEQ_LEN   256
#define LABEL_LEN 128
#define BATCH     8192
#define NF        8
#define NO        8
#define HID       64
#define G3        192   // 3*HID

#define ROWS      64                 // batch rows per CTA
#define NCTA      (BATCH / ROWS)     // 128
#define NTHREADS  256                // 16 (col groups) x 16 (row groups)

typedef unsigned long long u64;

struct Smem {
    __align__(16) float whh_t[HID * G3];       // [k][c] : Whh transposed
    __align__(16) float wih_t[NF * G3];        // [f][c]
    __align__(16) float wout_t[HID * NO];      // [k][o]
    __align__(16) float brz[2 * HID];          // bih + bhh for r,z gates
    __align__(16) float bin_[HID];             // bih n-gate
    __align__(16) float bhn[HID];              // bhh n-gate
    __align__(16) float bout_s[NO];
    __align__(16) float h_dup[HID * 2 * ROWS]; // [k][2*row] : h duplicated (h,h)
    __align__(16) float x_dup[NF * 2 * ROWS];  // [f][2*row] : input duplicated
};

__device__ __forceinline__ float sigf(float x) {
    return __fdividef(1.0f, 1.0f + __expf(-x));
}
__device__ __forceinline__ float tanh_(float x) {
    return __fdividef(2.0f, 1.0f + __expf(-2.0f * x)) - 1.0f;
}

__device__ __forceinline__ u64 fma2(u64 a, u64 b, u64 c) {
    u64 d;
    asm("fma.rn.f32x2 %0, %1, %2, %3;" : "=l"(d) : "l"(a), "l"(b), "l"(c));
    return d;
}
__device__ __forceinline__ float2 unpack2(u64 v) {
    float2 r;
    asm("mov.b64 {%0, %1}, %2;" : "=f"(r.x), "=f"(r.y) : "l"(v));
    return r;
}

__device__ void load_phase_weights(Smem* s, const float* Wih, const float* Whh,
                                   const float* bih, const float* bhh) {
    int tid = threadIdx.x;
    for (int idx = tid; idx < G3 * HID; idx += NTHREADS) {
        int c = idx / HID, k = idx % HID;
        s->whh_t[k * G3 + c] = Whh[idx];
    }
    for (int idx = tid; idx < G3 * NF; idx += NTHREADS) {
        int c = idx / NF, f = idx % NF;
        s->wih_t[f * G3 + c] = Wih[idx];
    }
    for (int c = tid; c < 2 * HID; c += NTHREADS) s->brz[c] = bih[c] + bhh[c];
    for (int c = tid; c < HID; c += NTHREADS) {
        s->bin_[c] = bih[2 * HID + c];
        s->bhn[c]  = bhh[2 * HID + c];
    }
}

// One GRU step. Preconditions: x_dup, h_dup populated and synced.
// Postcondition: h_dup updated, synced.
__device__ __forceinline__ void gru_step(Smem* s, int tx, int ty) {
    const int c0 = tx * 4;   // hidden-column group (0..60)
    const int r0 = ty * 4;   // batch-row group (0..60)

    // Accumulators: f32x2 pairs over j (columns c0+0/1 and c0+2/3), 4 rows.
    u64 ar[4][2], az[4][2], ai[4][2], ah[4][2];
    {
        const ulonglong2 br = *(const ulonglong2*)&s->brz[c0];
        const ulonglong2 bz = *(const ulonglong2*)&s->brz[HID + c0];
        const ulonglong2 bi = *(const ulonglong2*)&s->bin_[c0];
        const ulonglong2 bh = *(const ulonglong2*)&s->bhn[c0];
        #pragma unroll
        for (int i = 0; i < 4; i++) {
            ar[i][0] = br.x; ar[i][1] = br.y;
            az[i][0] = bz.x; az[i][1] = bz.y;
            ai[i][0] = bi.x; ai[i][1] = bi.y;
            ah[i][0] = bh.x; ah[i][1] = bh.y;
        }
    }

    // Input contribution (k over NF=8): r, z, and in-part of n
    #pragma unroll
    for (int k = 0; k < NF; k++) {
        const float* xd = &s->x_dup[k * 2 * ROWS + 2 * r0];
        const ulonglong2 xpA = *(const ulonglong2*)xd;        // (x0,x0),(x1,x1)
        const ulonglong2 xpB = *(const ulonglong2*)(xd + 4);  // (x2,x2),(x3,x3)
        const u64 xp[4] = {xpA.x, xpA.y, xpB.x, xpB.y};
        const ulonglong2 wr = *(const ulonglong2*)&s->wih_t[k * G3 + c0];
        const ulonglong2 wz = *(const ulonglong2*)&s->wih_t[k * G3 + HID + c0];
        const ulonglong2 wn = *(const ulonglong2*)&s->wih_t[k * G3 + 2 * HID + c0];
        #pragma unroll
        for (int i = 0; i < 4; i++) {
            ar[i][0] = fma2(xp[i], wr.x, ar[i][0]);
            ar[i][1] = fma2(xp[i], wr.y, ar[i][1]);
            az[i][0] = fma2(xp[i], wz.x, az[i][0]);
            az[i][1] = fma2(xp[i], wz.y, az[i][1]);
            ai[i][0] = fma2(xp[i], wn.x, ai[i][0]);
            ai[i][1] = fma2(xp[i], wn.y, ai[i][1]);
        }
    }

    // Hidden contribution (k over HID=64): r, z, and h-part of n
    #pragma unroll 4
    for (int k = 0; k < HID; k++) {
        const float* hd = &s->h_dup[k * 2 * ROWS + 2 * r0];
        const ulonglong2 hpA = *(const ulonglong2*)hd;
        const ulonglong2 hpB = *(const ulonglong2*)(hd + 4);
        const u64 hp[4] = {hpA.x, hpA.y, hpB.x, hpB.y};
        const ulonglong2 wr = *(const ulonglong2*)&s->whh_t[k * G3 + c0];
        const ulonglong2 wz = *(const ulonglong2*)&s->whh_t[k * G3 + HID + c0];
        const ulonglong2 wn = *(const ulonglong2*)&s->whh_t[k * G3 + 2 * HID + c0];
        #pragma unroll
        for (int i = 0; i < 4; i++) {
            ar[i][0] = fma2(hp[i], wr.x, ar[i][0]);
            ar[i][1] = fma2(hp[i], wr.y, ar[i][1]);
            az[i][0] = fma2(hp[i], wz.x, az[i][0]);
            az[i][1] = fma2(hp[i], wz.y, az[i][1]);
            ah[i][0] = fma2(hp[i], wn.x, ah[i][0]);
            ah[i][1] = fma2(hp[i], wn.y, ah[i][1]);
        }
    }

    // Unpack accumulators to scalars
    float Ar[4][4], Az[4][4], Ai[4][4], Ah[4][4];
    #pragma unroll
    for (int i = 0; i < 4; i++)
        #pragma unroll
        for (int jp = 0; jp < 2; jp++) {
            float2 t;
            t = unpack2(ar[i][jp]); Ar[i][2*jp] = t.x; Ar[i][2*jp+1] = t.y;
            t = unpack2(az[i][jp]); Az[i][2*jp] = t.x; Az[i][2*jp+1] = t.y;
            t = unpack2(ai[i][jp]); Ai[i][2*jp] = t.x; Ai[i][2*jp+1] = t.y;
            t = unpack2(ah[i][jp]); Ah[i][2*jp] = t.x; Ah[i][2*jp+1] = t.y;
        }

    // Gates + state update. hnew[j][i] layout for the transposed dup store.
    float hnew[4][4];
    #pragma unroll
    for (int j = 0; j < 4; j++) {
        const float* hd = &s->h_dup[(c0 + j) * 2 * ROWS + 2 * r0];
        const float4 h01 = *(const float4*)hd;        // (h0,h0,h1,h1)
        const float4 h23 = *(const float4*)(hd + 4);  // (h2,h2,h3,h3)
        const float hoa[4] = {h01.x, h01.z, h23.x, h23.z};
        #pragma unroll
        for (int i = 0; i < 4; i++) {
            float r = sigf(Ar[i][j]);
            float z = sigf(Az[i][j]);
            float n = tanh_(fmaf(r, Ah[i][j], Ai[i][j]));
            hnew[j][i] = fmaf(z, hoa[i] - n, n);   // (1-z)*n + z*h
        }
    }
    __syncthreads();   // all reads of old h_dup complete
    #pragma unroll
    for (int j = 0; j < 4; j++) {
        float* hd = &s->h_dup[(c0 + j) * 2 * ROWS + 2 * r0];
        *(float4*)hd       = make_float4(hnew[j][0], hnew[j][0], hnew[j][1], hnew[j][1]);
        *(float4*)(hd + 4) = make_float4(hnew[j][2], hnew[j][2], hnew[j][3], hnew[j][3]);
    }
    __syncthreads();   // new h_dup visible
}

extern __shared__ __align__(16) float smem_raw[];

__global__ void __launch_bounds__(NTHREADS)
seq2seq_gru_kernel(const float* __restrict__ x,  const float* __restrict__ xy,
                   const float* __restrict__ eWih, const float* __restrict__ eWhh,
                   const float* __restrict__ ebih, const float* __restrict__ ebhh,
                   const float* __restrict__ dWih, const float* __restrict__ dWhh,
                   const float* __restrict__ dbih, const float* __restrict__ dbhh,
                   const float* __restrict__ Wout, const float* __restrict__ bout,
                   float* __restrict__ out)
{
    Smem* s = (Smem*)smem_raw;
    const int tid = threadIdx.x;
    const int tx = tid % 16;
    const int ty = tid / 16;
    const int b0 = blockIdx.x * ROWS;

    // init h = 0
    for (int i = tid; i < HID * 2 * ROWS; i += NTHREADS) s->h_dup[i] = 0.0f;

    load_phase_weights(s, eWih, eWhh, ebih, ebhh);

    for (int idx = tid; idx < HID * NO; idx += NTHREADS) {
        int o = idx / HID, k = idx % HID;
        s->wout_t[k * NO + o] = Wout[idx];
    }
    if (tid < NO) s->bout_s[tid] = bout[tid];
    __syncthreads();

    // ----- Encoder: 256 steps -----
    for (int t = 0; t < SEQ_LEN; t++) {
        if (tid < ROWS) {
            const float* xr = x + ((size_t)t * BATCH + b0 + tid) * NF;
            float4 a = *(const float4*)xr;
            float4 b = *(const float4*)(xr + 4);
            const float v[8] = {a.x, a.y, a.z, a.w, b.x, b.y, b.z, b.w};
            #pragma unroll
            for (int f = 0; f < NF; f++)
                *(float2*)&s->x_dup[f * 2 * ROWS + 2 * tid] = make_float2(v[f], v[f]);
        }
        __syncthreads();
        gru_step(s, tx, ty);
    }

    // ----- Switch to decoder weights; seed input with xy[0] -----
    load_phase_weights(s, dWih, dWhh, dbih, dbhh);
    if (tid < ROWS) {
        const float* xr = xy + ((size_t)b0 + tid) * NO;   // xy[0]
        float4 a = *(const float4*)xr;
        float4 b = *(const float4*)(xr + 4);
        const float v[8] = {a.x, a.y, a.z, a.w, b.x, b.y, b.z, b.w};
        #pragma unroll
        for (int f = 0; f < NO; f++)
            *(float2*)&s->x_dup[f * 2 * ROWS + 2 * tid] = make_float2(v[f], v[f]);
    }
    __syncthreads();

    // ----- Decoder: 128 steps, autoregressive through output projection -----
    for (int t = 0; t < LABEL_LEN; t++) {
        gru_step(s, tx, ty);   // consumes x_dup, updates h_dup (ends synced)

        // Output projection: 64 rows x 8 outs = 512 dots; 2 per thread.
        const int o    = tid & 7;
        const int row0 = tid >> 3;        // 0..31
        const int row1 = row0 + 32;
        float acc0 = 0.0f, acc1 = 0.0f;
        #pragma unroll 8
        for (int k = 0; k < HID; k++) {
            const float w = s->wout_t[k * NO + o];
            acc0 = fmaf(s->h_dup[k * 2 * ROWS + 2 * row0], w, acc0);
            acc1 = fmaf(s->h_dup[k * 2 * ROWS + 2 * row1], w, acc1);
        }
        acc0 += s->bout_s[o];
        acc1 += s->bout_s[o];

        float* op = out + ((size_t)t * BATCH + b0) * NO;
        op[row0 * NO + o] = acc0;
        op[row1 * NO + o] = acc1;

        // Feed back as next decoder input (duplicated pairs)
        *(float2*)&s->x_dup[o * 2 * ROWS + 2 * row0] = make_float2(acc0, acc0);
        *(float2*)&s->x_dup[o * 2 * ROWS + 2 * row1] = make_float2(acc1, acc1);
        __syncthreads();
    }
}

extern "C" void kernel_launch(void* const* d_in, const int* in_sizes, int n_in,
                              void* d_out, int out_size) {
    const float* x    = (const float*)d_in[0];
    const float* xy   = (const float*)d_in[1];
    const float* eWih = (const float*)d_in[2];
    const float* eWhh = (const float*)d_in[3];
    const float* ebih = (const float*)d_in[4];
    const float* ebhh = (const float*)d_in[5];
    const float* dWih = (const float*)d_in[6];
    const float* dWhh = (const float*)d_in[7];
    const float* dbih = (const float*)d_in[8];
    const float* dbhh = (const float*)d_in[9];
    const float* Wout = (const float*)d_in[10];
    const float* bout = (const float*)d_in[11];
    float* out = (float*)d_out;

    const int smem_bytes = (int)sizeof(Smem);
    cudaFuncSetAttribute(seq2seq_gru_kernel,
                         cudaFuncAttributeMaxDynamicSharedMemorySize, smem_bytes);

    seq2seq_gru_kernel<<<NCTA, NTHREADS, smem_bytes>>>(
        x, xy, eWih, eWhh, ebih, ebhh, dWih, dWhh, dbih, dbhh, Wout, bout, out);
}